// round 14
// baseline (speedup 1.0000x reference)
#include <cuda_runtime.h>

#define BB 32
#define NN 2048
#define HH 512
#define NCH 16           // n-chunks per batch for the fused pass
#define NPC (NN/NCH)     // 128 rows per chunk
#define RPW (NPC/16)     // rows per warp in phase 1 = 8

// ---- scratch (device globals; no allocation allowed) ----
__device__ float g_p[BB*NN];              // unnormalized exp weights
__device__ float g_psum[BB*NCH];          // partial sums of p
__device__ float g_upart[BB*NCH*2*HH];    // partial weighted-V sums
__device__ float g_u[BB*2*HH];            // normalized u0|u1

__device__ __forceinline__ float warp_sum(float v) {
#pragma unroll
    for (int o = 16; o; o >>= 1) v += __shfl_xor_sync(0xffffffffu, v, o);
    return v;
}

// ---------------- fused: qdot, alpha -> p = adj*exp(alpha), weighted V partials ----------------
// ROUND-8 VERSION VERBATIM (measured 45.2-46.0us @ ~76% DRAM). PROTECTED.
// No max-subtraction needed: alpha ~ N(0,~0.8) => max over 64k ~ 3.5; exp safe.
__global__ void __launch_bounds__(512, 2)
k_fused(const float* __restrict__ Q,
        const float* __restrict__ K,
        const float* __restrict__ V,
        const float* __restrict__ w_att,
        const float* __restrict__ b_att,
        const int*   __restrict__ adj,
        const int*   __restrict__ s_mask) {
    __shared__ float wk[HH];
    __shared__ float sw0[NPC], sw1[NPC];
    __shared__ float sred[16];
    __shared__ float s_qd;
    __shared__ float4 red0[512], red1[512];

    int b = blockIdx.y, c = blockIdx.x;
    int n0 = c * NPC;
    int t = threadIdx.x;
    int w = t >> 5, l = t & 31;

    wk[t] = w_att[HH + t];

    // ---- phase 0: qdot for this b ----
    float qv = Q[b * HH + t] * w_att[t];
    qv = warp_sum(qv);
    if (l == 0) sred[w] = qv;
    __syncthreads();
    if (t == 0) {
        float s = 0.f;
#pragma unroll
        for (int i = 0; i < 16; i++) s += sred[i];
        s_qd = s + b_att[0];
    }
    __syncthreads();
    float qd = s_qd;

    // ---- phase 1: p for 128 rows (16 warps x 8 rows, batched loads then batched reductions) ----
    const float4* wk4 = (const float4*)wk;
    float4 wv0 = wk4[l], wv1 = wk4[32 + l], wv2 = wk4[64 + l], wv3 = wk4[96 + l];

    float sacc[RPW];
    const float4* kbase = (const float4*)(K + ((size_t)b * NN + n0 + w * RPW) * HH);
#pragma unroll
    for (int j = 0; j < RPW; j++) {
        const float4* kp = kbase + (size_t)j * (HH / 4);
        float4 k0 = kp[l], k1 = kp[32 + l], k2 = kp[64 + l], k3 = kp[96 + l];
        float s;
        s  = k0.x * wv0.x + k0.y * wv0.y + k0.z * wv0.z + k0.w * wv0.w;
        s += k1.x * wv1.x + k1.y * wv1.y + k1.z * wv1.z + k1.w * wv1.w;
        s += k2.x * wv2.x + k2.y * wv2.y + k2.z * wv2.z + k2.w * wv2.w;
        s += k3.x * wv3.x + k3.y * wv3.y + k3.z * wv3.z + k3.w * wv3.w;
        sacc[j] = s;
    }
#pragma unroll
    for (int j = 0; j < RPW; j++) {
        float s = warp_sum(sacc[j]);
        if (l == 0) {
            int r = w * RPW + j;
            int gi = b * NN + n0 + r;
            float p = adj[gi] ? __expf(s + qd) : 0.f;
            int smv = s_mask[gi];
            sw0[r] = smv ? p : 0.f;
            sw1[r] = smv ? 0.f : p;
            g_p[gi] = p;
        }
    }
    __syncthreads();

    // partial psum (warp 0; overlaps with start of phase 2 on other warps)
    if (w == 0) {
        float ps = 0.f;
#pragma unroll
        for (int i = 0; i < NPC / 32; i++) ps += sw0[i * 32 + l] + sw1[i * 32 + l];
        ps = warp_sum(ps);
        if (l == 0) g_psum[b * NCH + c] = ps;
    }

    // ---- phase 2: weighted V accumulation (float4, 4-way row split) ----
    int h4 = t & 127;                                  // float4 column 0..127
    int rg = t >> 7;                                   // row group 0..3
    const float4* vp = (const float4*)V + ((size_t)b * NN + n0 + rg * (NPC / 4)) * (HH / 4) + h4;
    float4 a0 = make_float4(0.f, 0.f, 0.f, 0.f);
    float4 a1 = make_float4(0.f, 0.f, 0.f, 0.f);
#pragma unroll 8
    for (int i = 0; i < NPC / 4; i++) {               // 32 rows
        float4 v = __ldg(vp + (size_t)i * (HH / 4));
        float x0 = sw0[rg * (NPC / 4) + i];
        float x1 = sw1[rg * (NPC / 4) + i];
        a0.x += x0 * v.x; a0.y += x0 * v.y; a0.z += x0 * v.z; a0.w += x0 * v.w;
        a1.x += x1 * v.x; a1.y += x1 * v.y; a1.z += x1 * v.z; a1.w += x1 * v.w;
    }
    red0[t] = a0;
    red1[t] = a1;
    __syncthreads();
    if (t < 128) {
        float4 r0 = red0[t], r1 = red1[t];
#pragma unroll
        for (int g = 1; g < 4; g++) {
            float4 x = red0[t + g * 128];
            r0.x += x.x; r0.y += x.y; r0.z += x.z; r0.w += x.w;
            float4 y = red1[t + g * 128];
            r1.x += y.x; r1.y += y.y; r1.z += y.z; r1.w += y.w;
        }
        float4* up0 = (float4*)(g_upart + ((size_t)(b * NCH + c) * 2 + 0) * HH);
        float4* up1 = (float4*)(g_upart + ((size_t)(b * NCH + c) * 2 + 1) * HH);
        up0[t] = r0;
        up1[t] = r1;
    }
}

// ---------------- normalize: u = sum(upart)/sum(p); attn = p/sum(p) ----------------
// grid (8 slices, BB), 256 threads (round-8 version verbatim). PROTECTED.
__global__ void __launch_bounds__(256)
k_norm(float* __restrict__ out) {
    __shared__ float sinv;
    int sl = blockIdx.x, b = blockIdx.y;
    int t = threadIdx.x, l = t & 31;

    if (t < 32) {
        float ps = (l < NCH) ? g_psum[b * NCH + l] : 0.f;
        ps = warp_sum(ps);
        if (l == 0) sinv = 1.0f / ps;
    }
    __syncthreads();
    float inv = sinv;

    int ai = sl * 256 + t;
    out[b * NN + ai] = g_p[b * NN + ai] * inv;

    if (sl < 4) {
        int ui = sl * 256 + t;
        float s = 0.f;
#pragma unroll
        for (int cc = 0; cc < NCH; cc++)
            s += g_upart[(size_t)(b * NCH + cc) * 2 * HH + ui];
        g_u[b * 2 * HH + ui] = s * inv;
    }
}

// ---------------- epilogue v5: attn_sum[b,o] = u0·Wr0[o] + u1·Wr1[o] + Q[b]·Wri[o] ----------------
// grid (128 o-tiles of 4, 8 b-groups of 4) = 1024 blocks (~7/SM) — latency hidden
// by block count. One warp = one o x two b. Weights: 12 independent front-batched
// LDG.128 into 48 regs. u/Q for the 4-b group in 24KB smem (L2-hot across blocks).
__global__ void __launch_bounds__(256)
k_out(const float* __restrict__ Q,
      const float* __restrict__ Wr0,
      const float* __restrict__ Wr1,
      const float* __restrict__ Wri,
      float* __restrict__ out) {
    __shared__ float4 s_u[4][2*HH/4];      // 16KB: normalized u0|u1 per b
    __shared__ float4 s_q[4][HH/4];        // 8KB : Q rows
    int t = threadIdx.x, w = t >> 5, l = t & 31;
    int o    = blockIdx.x * 4 + (w & 3);
    int half = w >> 2;                     // which bb pair this warp handles
    int b0   = blockIdx.y * 4;

    // weights into registers (12 independent LDG.128, front-batched)
    const float4* w0g = (const float4*)(Wr0 + (size_t)o * HH);
    const float4* w1g = (const float4*)(Wr1 + (size_t)o * HH);
    const float4* wig = (const float4*)(Wri + (size_t)o * HH);
    float4 w0f[4], w1f[4], wif[4];
#pragma unroll
    for (int i = 0; i < 4; i++) {
        int idx = i * 32 + l;
        w0f[i] = w0g[idx];
        w1f[i] = w1g[idx];
        wif[i] = wig[idx];
    }

    // cooperative operand load: u = 1024 float4, q = 512 float4
#pragma unroll
    for (int rep = 0; rep < 4; rep++) {
        int idx = rep * 256 + t;
        int bb = idx >> 8, j4 = idx & 255;
        s_u[bb][j4] = ((const float4*)(g_u + (size_t)(b0 + bb) * 2 * HH))[j4];
    }
#pragma unroll
    for (int rep = 0; rep < 2; rep++) {
        int idx = rep * 256 + t;
        int bb = idx >> 7, j4 = idx & 127;
        s_q[bb][j4] = ((const float4*)(Q + (size_t)(b0 + bb) * HH))[j4];
    }
    __syncthreads();

    float acc[2];
#pragma unroll
    for (int bb2 = 0; bb2 < 2; bb2++) {
        int bb = half * 2 + bb2;
        float s = 0.f;
#pragma unroll
        for (int i = 0; i < 4; i++) {
            int idx = i * 32 + l;
            float4 u0 = s_u[bb][idx];
            float4 u1 = s_u[bb][128 + idx];
            float4 qv = s_q[bb][idx];
            s += u0.x * w0f[i].x + u0.y * w0f[i].y + u0.z * w0f[i].z + u0.w * w0f[i].w;
            s += u1.x * w1f[i].x + u1.y * w1f[i].y + u1.z * w1f[i].z + u1.w * w1f[i].w;
            s += qv.x * wif[i].x + qv.y * wif[i].y + qv.z * wif[i].z + qv.w * wif[i].w;
        }
        acc[bb2] = warp_sum(s);
    }
    if (l == 0) {
        out[BB * NN + (size_t)(b0 + half * 2 + 0) * HH + o] = acc[0];
        out[BB * NN + (size_t)(b0 + half * 2 + 1) * HH + o] = acc[1];
    }
}

// ---------------- launch ----------------
extern "C" void kernel_launch(void* const* d_in, const int* in_sizes, int n_in,
                              void* d_out, int out_size) {
    const float* Q     = (const float*)d_in[0];
    const float* K     = (const float*)d_in[1];
    const float* V     = (const float*)d_in[2];
    const int*   adj   = (const int*)d_in[3];
    const int*   smask = (const int*)d_in[4];
    const float* w_att = (const float*)d_in[5];
    const float* b_att = (const float*)d_in[6];
    const float* Wr0   = (const float*)d_in[7];
    const float* Wr1   = (const float*)d_in[8];
    const float* Wri   = (const float*)d_in[9];
    float* out = (float*)d_out;

    k_fused<<<dim3(NCH, BB), 512>>>(Q, K, V, w_att, b_att, adj, smask);
    k_norm<<<dim3(8, BB), 256>>>(out);
    k_out<<<dim3(128, 8), 256>>>(Q, Wr0, Wr1, Wri, out);
}

// round 15
// speedup vs baseline: 1.0314x; 1.0314x over previous
#include <cuda_runtime.h>

#define BB 32
#define NN 2048
#define HH 512
#define NCH 16           // n-chunks per batch for the fused pass
#define NPC (NN/NCH)     // 128 rows per chunk
#define RPW (NPC/8)      // rows per warp in phase 1 = 16 (8 warps)

// ---- scratch (device globals; no allocation allowed) ----
__device__ float g_p[BB*NN];              // unnormalized exp weights
__device__ float g_psum[BB*NCH];          // partial sums of p
__device__ float g_upart[BB*NCH*2*HH];    // partial weighted-V sums
__device__ float g_u[BB*2*HH];            // normalized u0|u1

__device__ __forceinline__ float warp_sum(float v) {
#pragma unroll
    for (int o = 16; o; o >>= 1) v += __shfl_xor_sync(0xffffffffu, v, o);
    return v;
}

// ---------------- fused: qdot, alpha -> p = adj*exp(alpha), weighted V partials ----------------
// SINGLE-WAVE variant: 256 threads, 4 blocks/SM (592 slots >= 512 blocks -> no
// wave-quantization tail). Same chunks (NCH=16, NPC=128) and per-block work as
// the round-8 version; per-thread work doubled (more front-batched MLP).
// No max-subtraction needed: alpha ~ N(0,~0.8) => max over 64k ~ 3.5; exp safe.
__global__ void __launch_bounds__(256, 4)
k_fused(const float* __restrict__ Q,
        const float* __restrict__ K,
        const float* __restrict__ V,
        const float* __restrict__ w_att,
        const float* __restrict__ b_att,
        const int*   __restrict__ adj,
        const int*   __restrict__ s_mask) {
    __shared__ float sw0[NPC], sw1[NPC];
    __shared__ float sred[8];
    __shared__ float s_qd;
    __shared__ float4 red0[256], red1[256];

    int b = blockIdx.y, c = blockIdx.x;
    int n0 = c * NPC;
    int t = threadIdx.x;
    int w = t >> 5, l = t & 31;

    // ---- phase 0: qdot for this b (2 elems/thread) ----
    float qv = Q[b * HH + t] * w_att[t] + Q[b * HH + t + 256] * w_att[t + 256];
    qv = warp_sum(qv);
    if (l == 0) sred[w] = qv;
    __syncthreads();
    if (t == 0) {
        float s = 0.f;
#pragma unroll
        for (int i = 0; i < 8; i++) s += sred[i];
        s_qd = s + b_att[0];
    }
    __syncthreads();
    float qd = s_qd;

    // ---- phase 1: p for 128 rows (8 warps x 16 rows; loads front-batched per ptxas window) ----
    const float4* wk4 = (const float4*)(w_att + HH);
    float4 wv0 = wk4[l], wv1 = wk4[32 + l], wv2 = wk4[64 + l], wv3 = wk4[96 + l];

    float sacc[RPW];
    const float4* kbase = (const float4*)(K + ((size_t)b * NN + n0 + w * RPW) * HH);
#pragma unroll
    for (int j = 0; j < RPW; j++) {
        const float4* kp = kbase + (size_t)j * (HH / 4);
        float4 k0 = kp[l], k1 = kp[32 + l], k2 = kp[64 + l], k3 = kp[96 + l];
        float s;
        s  = k0.x * wv0.x + k0.y * wv0.y + k0.z * wv0.z + k0.w * wv0.w;
        s += k1.x * wv1.x + k1.y * wv1.y + k1.z * wv1.z + k1.w * wv1.w;
        s += k2.x * wv2.x + k2.y * wv2.y + k2.z * wv2.z + k2.w * wv2.w;
        s += k3.x * wv3.x + k3.y * wv3.y + k3.z * wv3.z + k3.w * wv3.w;
        sacc[j] = s;
    }
#pragma unroll
    for (int j = 0; j < RPW; j++) {
        float s = warp_sum(sacc[j]);
        if (l == 0) {
            int r = w * RPW + j;
            int gi = b * NN + n0 + r;
            float p = adj[gi] ? __expf(s + qd) : 0.f;
            int smv = s_mask[gi];
            sw0[r] = smv ? p : 0.f;
            sw1[r] = smv ? 0.f : p;
            g_p[gi] = p;
        }
    }
    __syncthreads();

    // partial psum (warp 0; overlaps with start of phase 2 on other warps)
    if (w == 0) {
        float ps = 0.f;
#pragma unroll
        for (int i = 0; i < NPC / 32; i++) ps += sw0[i * 32 + l] + sw1[i * 32 + l];
        ps = warp_sum(ps);
        if (l == 0) g_psum[b * NCH + c] = ps;
    }

    // ---- phase 2: weighted V accumulation (float4, 2-way row split, 64 iters/thread) ----
    int h4 = t & 127;                                  // float4 column 0..127
    int rg = t >> 7;                                   // row group 0..1
    const float4* vp = (const float4*)V + ((size_t)b * NN + n0 + rg * (NPC / 2)) * (HH / 4) + h4;
    float4 a0 = make_float4(0.f, 0.f, 0.f, 0.f);
    float4 a1 = make_float4(0.f, 0.f, 0.f, 0.f);
#pragma unroll 8
    for (int i = 0; i < NPC / 2; i++) {               // 64 rows
        float4 v = __ldg(vp + (size_t)i * (HH / 4));
        float x0 = sw0[rg * (NPC / 2) + i];
        float x1 = sw1[rg * (NPC / 2) + i];
        a0.x += x0 * v.x; a0.y += x0 * v.y; a0.z += x0 * v.z; a0.w += x0 * v.w;
        a1.x += x1 * v.x; a1.y += x1 * v.y; a1.z += x1 * v.z; a1.w += x1 * v.w;
    }
    red0[t] = a0;
    red1[t] = a1;
    __syncthreads();
    if (t < 128) {
        float4 r0 = red0[t], r1 = red1[t];
        float4 x = red0[t + 128];
        r0.x += x.x; r0.y += x.y; r0.z += x.z; r0.w += x.w;
        float4 y = red1[t + 128];
        r1.x += y.x; r1.y += y.y; r1.z += y.z; r1.w += y.w;
        float4* up0 = (float4*)(g_upart + ((size_t)(b * NCH + c) * 2 + 0) * HH);
        float4* up1 = (float4*)(g_upart + ((size_t)(b * NCH + c) * 2 + 1) * HH);
        up0[t] = r0;
        up1[t] = r1;
    }
}

// ---------------- normalize: u = sum(upart)/sum(p); attn = p/sum(p) ----------------
// grid (8 slices, BB), 256 threads (round-8 version verbatim). PROTECTED.
__global__ void __launch_bounds__(256)
k_norm(float* __restrict__ out) {
    __shared__ float sinv;
    int sl = blockIdx.x, b = blockIdx.y;
    int t = threadIdx.x, l = t & 31;

    if (t < 32) {
        float ps = (l < NCH) ? g_psum[b * NCH + l] : 0.f;
        ps = warp_sum(ps);
        if (l == 0) sinv = 1.0f / ps;
    }
    __syncthreads();
    float inv = sinv;

    int ai = sl * 256 + t;
    out[b * NN + ai] = g_p[b * NN + ai] * inv;

    if (sl < 4) {
        int ui = sl * 256 + t;
        float s = 0.f;
#pragma unroll
        for (int cc = 0; cc < NCH; cc++)
            s += g_upart[(size_t)(b * NCH + cc) * 2 * HH + ui];
        g_u[b * 2 * HH + ui] = s * inv;
    }
}

// ---------------- epilogue: attn_sum[b,o] = u0·Wr0[o] + u1·Wr1[o] + Q[b]·Wri[o] ----------------
// Round-11 v3 (measured ok): grid (64 o-tiles, 8 b-groups), 256 threads;
// u/Q in smem, weights front-batched into 48 regs.
__global__ void __launch_bounds__(256)
k_out(const float* __restrict__ Q,
      const float* __restrict__ Wr0,
      const float* __restrict__ Wr1,
      const float* __restrict__ Wri,
      float* __restrict__ out) {
    __shared__ float4 s_u0[4][HH/4], s_u1[4][HH/4], s_q[4][HH/4];
    int t = threadIdx.x, w = t >> 5, l = t & 31;
    int o  = blockIdx.x * 8 + w;
    int b0 = blockIdx.y * 4;

#pragma unroll
    for (int j = 0; j < 2; j++) {
        int idx = j * 256 + t;
        int bb = idx >> 7, h4 = idx & 127;
        s_u0[bb][h4] = ((const float4*)(g_u + (size_t)(b0 + bb) * 2 * HH))[h4];
        s_u1[bb][h4] = ((const float4*)(g_u + (size_t)(b0 + bb) * 2 * HH + HH))[h4];
        s_q [bb][h4] = ((const float4*)(Q + (size_t)(b0 + bb) * HH))[h4];
    }

    const float4* w0g = (const float4*)(Wr0 + (size_t)o * HH);
    const float4* w1g = (const float4*)(Wr1 + (size_t)o * HH);
    const float4* wig = (const float4*)(Wri + (size_t)o * HH);
    float4 w0f[4], w1f[4], wif[4];
#pragma unroll
    for (int i = 0; i < 4; i++) {
        int idx = i * 32 + l;
        w0f[i] = w0g[idx];
        w1f[i] = w1g[idx];
        wif[i] = wig[idx];
    }
    __syncthreads();

    float acc[4];
#pragma unroll
    for (int bb = 0; bb < 4; bb++) {
        float s = 0.f;
#pragma unroll
        for (int i = 0; i < 4; i++) {
            int idx = i * 32 + l;
            float4 u0 = s_u0[bb][idx];
            float4 u1 = s_u1[bb][idx];
            float4 qv = s_q[bb][idx];
            s += u0.x * w0f[i].x + u0.y * w0f[i].y + u0.z * w0f[i].z + u0.w * w0f[i].w;
            s += u1.x * w1f[i].x + u1.y * w1f[i].y + u1.z * w1f[i].z + u1.w * w1f[i].w;
            s += qv.x * wif[i].x + qv.y * wif[i].y + qv.z * wif[i].z + qv.w * wif[i].w;
        }
        acc[bb] = warp_sum(s);
    }
    if (l == 0) {
#pragma unroll
        for (int bb = 0; bb < 4; bb++)
            out[BB * NN + (size_t)(b0 + bb) * HH + o] = acc[bb];
    }
}

// ---------------- launch ----------------
extern "C" void kernel_launch(void* const* d_in, const int* in_sizes, int n_in,
                              void* d_out, int out_size) {
    const float* Q     = (const float*)d_in[0];
    const float* K     = (const float*)d_in[1];
    const float* V     = (const float*)d_in[2];
    const int*   adj   = (const int*)d_in[3];
    const int*   smask = (const int*)d_in[4];
    const float* w_att = (const float*)d_in[5];
    const float* b_att = (const float*)d_in[6];
    const float* Wr0   = (const float*)d_in[7];
    const float* Wr1   = (const float*)d_in[8];
    const float* Wri   = (const float*)d_in[9];
    float* out = (float*)d_out;

    k_fused<<<dim3(NCH, BB), 256>>>(Q, K, V, w_att, b_att, adj, smask);
    k_norm<<<dim3(8, BB), 256>>>(out);
    k_out<<<dim3(64, 8), 256>>>(Q, Wr0, Wr1, Wri, out);
}